// round 14
// baseline (speedup 1.0000x reference)
#include <cuda_runtime.h>
#include <math.h>

#define B_ 2
#define S_ 2048
#define D_ 1024
#define H_ 16
#define DK_ 64
#define NROWS (B_*S_)      // 4096
#define NBH (B_*H_)        // 32

// Scratch (allocation-free): module-load static device memory
__device__ float g_Q[NBH*S_*DK_];   // [b,h,s,dk]
__device__ float g_K[NBH*S_*DK_];
__device__ float g_V[NBH*S_*DK_];
__device__ float g_ctx[(size_t)NROWS*D_];
__device__ float g_rmax[NBH*S_];
__device__ float g_rinv[NBH*S_];

// ---------------------------------------------------------------------------
// bf16x3 helpers: split fp32 into bf16 hi + bf16 lo (≈16 mantissa bits),
// compute hh + hl + lh with bf16 m16n8k16 MMAs (fp32 accumulate).
// ---------------------------------------------------------------------------
// pack {low=x (k even), high=y (k odd)} as bf16x2
__device__ __forceinline__ unsigned packb2(float x, float y) {
    unsigned u;
    asm("cvt.rn.bf16x2.f32 %0, %1, %2;" : "=r"(u) : "f"(y), "f"(x));
    return u;
}
__device__ __forceinline__ void splitb2(float x, float y, unsigned &h, unsigned &l) {
    h = packb2(x, y);
    float hx = __uint_as_float((h & 0xffffu) << 16);
    float hy = __uint_as_float(h & 0xffff0000u);
    l = packb2(x - hx, y - hy);
}
// split a float4 (4 consecutive k) into 2 hi-u32 and 2 lo-u32 (pair-packed)
__device__ __forceinline__ void splitf4(unsigned* h2, unsigned* l2, float4 v) {
    splitb2(v.x, v.y, h2[0], l2[0]);
    splitb2(v.z, v.w, h2[1], l2[1]);
}

// bf16 m16n8k16 mma, accumulate into c[4]
__device__ __forceinline__ void mma16(float* c, const unsigned* a, unsigned b0, unsigned b1) {
    asm volatile(
        "mma.sync.aligned.m16n8k16.row.col.f32.bf16.bf16.f32 "
        "{%0,%1,%2,%3},{%4,%5,%6,%7},{%8,%9},{%0,%1,%2,%3};\n"
        : "+f"(c[0]), "+f"(c[1]), "+f"(c[2]), "+f"(c[3])
        : "r"(a[0]), "r"(a[1]), "r"(a[2]), "r"(a[3]), "r"(b0), "r"(b1));
}
// Fragment indexing (m16n8k16 bf16, pair-units: 1 u32 = 2 k-values):
//  g = lane>>2, tg = lane&3
//  A[m][kp]: a0=(g,tg) a1=(g+8,tg) a2=(g,tg+4) a3=(g+8,tg+4)
//  B^T[n][kp]: b0=(n=g row, tg) b1=(g, tg+4)
//  C[m][n]: c0=(g,2tg) c1=(g,2tg+1) c2=(g+8,2tg) c3=(g+8,2tg+1)  (same as tf32)

// tf32 helpers (av kernel keeps 1xTF32)
__device__ __forceinline__ unsigned cvt_tf32(float f) {
    unsigned u; asm("cvt.rna.tf32.f32 %0, %1;" : "=r"(u) : "f"(f)); return u;
}
__device__ __forceinline__ void cvt4(unsigned* h, float4 v) {
    h[0] = cvt_tf32(v.x); h[1] = cvt_tf32(v.y);
    h[2] = cvt_tf32(v.z); h[3] = cvt_tf32(v.w);
}
__device__ __forceinline__ void mma8(float* c, const unsigned* a, unsigned b0, unsigned b1) {
    asm volatile(
        "mma.sync.aligned.m16n8k8.row.col.f32.tf32.tf32.f32 "
        "{%0,%1,%2,%3},{%4,%5,%6,%7},{%8,%9},{%0,%1,%2,%3};\n"
        : "+f"(c[0]), "+f"(c[1]), "+f"(c[2]), "+f"(c[3])
        : "r"(a[0]), "r"(a[1]), "r"(a[2]), "r"(a[3]), "r"(b0), "r"(b1));
}

#define ASTR 20   // u32 stride for [128 rows][16 pairs] bf16 tiles (20%32=20 -> 4g+tg-ish distinct, verified)
#define QSTRP 36  // u32 stride for [128 rows][32 pairs] Q tiles (36%32=4 -> 4g+tg distinct)
#define PSTR 36   // tf32 [row][32] tiles (av kernel)
#define VSTR 72   // tf32 V [k][64] tiles (av kernel)

// ---------------------------------------------------------------------------
// Kernel 1: QKV projections (bf16x3), 256 threads, warp tile 64x32,
// register-prefetch double buffering.
// ---------------------------------------------------------------------------
__global__ void __launch_bounds__(256) proj_kernel(
    const float* __restrict__ Xq, const float* __restrict__ Xk, const float* __restrict__ Xv,
    const float* __restrict__ Wq, const float* __restrict__ bq,
    const float* __restrict__ Wk, const float* __restrict__ bk,
    const float* __restrict__ Wv, const float* __restrict__ bv)
{
    const int which = blockIdx.z;
    const float* X    = (which == 0) ? Xq : (which == 1) ? Xk : Xv;
    const float* W    = (which == 0) ? Wq : (which == 1) ? Wk : Wv;
    const float* bias = (which == 0) ? bq : (which == 1) ? bk : bv;
    float* Out        = (which == 0) ? g_Q : (which == 1) ? g_K : g_V;

    extern __shared__ unsigned sm[];
    unsigned (*Ah)[ASTR] = (unsigned(*)[ASTR])sm;   // 128 x 20
    unsigned (*Al)[ASTR] = Ah + 128;
    unsigned (*Bh)[ASTR] = Al + 128;
    unsigned (*Bl)[ASTR] = Bh + 128;

    const int tid = threadIdx.x;
    const int warp = tid >> 5;
    const int g = (tid >> 2) & 7, tg = tid & 3;
    const int wm0 = (warp & 1) * 64, wn0 = (warp >> 1) * 32;
    const int row0 = blockIdx.y * 128;
    const int col0 = blockIdx.x * 128;
    const int lr = tid >> 3;                 // 32 rows per pass
    const int lcf = (tid & 7) << 2;          // float col
    const int pc  = (tid & 7) << 1;          // pair col

    float acc[4][4][4] = {};
    float4 pa[4], pb[4];

    #pragma unroll
    for (int p = 0; p < 4; p++) {
        pa[p] = *reinterpret_cast<const float4*>(X + (size_t)(row0 + lr + p * 32) * D_ + lcf);
        pb[p] = *reinterpret_cast<const float4*>(W + (size_t)(col0 + lr + p * 32) * D_ + lcf);
    }

    for (int kb = 0; kb < D_; kb += 32) {
        #pragma unroll
        for (int p = 0; p < 4; p++) {
            int r = lr + p * 32;
            splitf4(&Ah[r][pc], &Al[r][pc], pa[p]);
            splitf4(&Bh[r][pc], &Bl[r][pc], pb[p]);
        }
        __syncthreads();
        if (kb + 32 < D_) {
            #pragma unroll
            for (int p = 0; p < 4; p++) {
                pa[p] = *reinterpret_cast<const float4*>(X + (size_t)(row0 + lr + p * 32) * D_ + kb + 32 + lcf);
                pb[p] = *reinterpret_cast<const float4*>(W + (size_t)(col0 + lr + p * 32) * D_ + kb + 32 + lcf);
            }
        }
        #pragma unroll
        for (int kp = 0; kp < 2; kp++) {       // two k16 blocks per 32-float chunk
            const int p0 = kp * 8;
            unsigned ah[4][4], al[4][4];
            #pragma unroll
            for (int mf = 0; mf < 4; mf++) {
                int r = wm0 + mf * 16;
                ah[mf][0] = Ah[r+g  ][p0+tg]; ah[mf][1] = Ah[r+g+8][p0+tg];
                ah[mf][2] = Ah[r+g  ][p0+tg+4]; ah[mf][3] = Ah[r+g+8][p0+tg+4];
                al[mf][0] = Al[r+g  ][p0+tg]; al[mf][1] = Al[r+g+8][p0+tg];
                al[mf][2] = Al[r+g  ][p0+tg+4]; al[mf][3] = Al[r+g+8][p0+tg+4];
            }
            #pragma unroll
            for (int nf = 0; nf < 4; nf++) {
                int r = wn0 + nf * 8 + g;
                unsigned bh0 = Bh[r][p0+tg], bh1 = Bh[r][p0+tg+4];
                unsigned bl0 = Bl[r][p0+tg], bl1 = Bl[r][p0+tg+4];
                #pragma unroll
                for (int mf = 0; mf < 4; mf++) {
                    mma16(acc[mf][nf], ah[mf], bh0, bh1);
                    mma16(acc[mf][nf], ah[mf], bl0, bl1);
                    mma16(acc[mf][nf], al[mf], bh0, bh1);
                }
            }
        }
        __syncthreads();
    }

    // Epilogue: bias + split-head store Out[((b*H+h)*S+s)*DK+dk]
    #pragma unroll
    for (int nf = 0; nf < 4; nf++) {
        int n0 = col0 + wn0 + nf * 8 + 2 * tg;
        float b0v = bias[n0], b1v = bias[n0 + 1];
        int h = n0 >> 6, dk = n0 & (DK_ - 1);
        #pragma unroll
        for (int mf = 0; mf < 4; mf++) {
            int m = row0 + wm0 + mf * 16 + g;
            int b = m >> 11, s = m & (S_ - 1);
            size_t base = (((size_t)(b * H_ + h)) * S_) * DK_ + dk;
            float2 o0 = make_float2(acc[mf][nf][0] + b0v, acc[mf][nf][1] + b1v);
            float2 o1 = make_float2(acc[mf][nf][2] + b0v, acc[mf][nf][3] + b1v);
            *reinterpret_cast<float2*>(&Out[base + (size_t)s * DK_])       = o0;
            *reinterpret_cast<float2*>(&Out[base + (size_t)(s + 8) * DK_]) = o1;
        }
    }
}

// ---------------------------------------------------------------------------
// Kernel 2: scores = (Q*scale) @ K^T (bf16x3) + fused online softmax stats,
// register prefetch of K chunks. 256 threads, warp owns 16 q rows.
// ---------------------------------------------------------------------------
__global__ void __launch_bounds__(256) scores_kernel(float* __restrict__ attn)
{
    extern __shared__ unsigned sm[];
    unsigned (*Qh)[QSTRP] = (unsigned(*)[QSTRP])sm;          // 128 x 36 (32 pairs)
    unsigned (*Ql)[QSTRP] = Qh + 128;
    unsigned (*Kh)[ASTR]  = (unsigned(*)[ASTR])(Ql + 128);   // 128 x 20 (16 pairs)
    unsigned (*Kl)[ASTR]  = Kh + 128;

    const int bh   = blockIdx.y;
    const int row0 = blockIdx.x * 128;
    const int tid  = threadIdx.x;
    const int warp = tid >> 5;
    const int g = (tid >> 2) & 7, tg = tid & 3;
    const int wm0 = warp * 16;
    const int lr = tid >> 3, lcf = (tid & 7) << 2, pc = (tid & 7) << 1;
    const int NT = S_ / 128;

    const float* Qm = g_Q + ((size_t)bh * S_ + row0) * DK_;
    const float* Km = g_K + (size_t)bh * S_ * DK_;

    // Stage whole Q strip (128 x 64 floats = 32 pairs), scaled, hi/lo split.
    #pragma unroll
    for (int p = 0; p < 8; p++) {
        int lin = tid + (p << 8);
        int r = lin >> 4, cf = (lin & 15) << 2;
        float4 v = *reinterpret_cast<const float4*>(Qm + (size_t)r * DK_ + cf);
        v.x *= 0.125f; v.y *= 0.125f; v.z *= 0.125f; v.w *= 0.125f;
        splitf4(&Qh[r][cf >> 1], &Ql[r][cf >> 1], v);
    }

    float4 pk[4];
    #pragma unroll
    for (int p = 0; p < 4; p++)
        pk[p] = *reinterpret_cast<const float4*>(Km + (size_t)(lr + p * 32) * DK_ + lcf);

    float m0 = -1e30f, m1 = -1e30f, s0 = 0.f, s1 = 0.f;

    for (int ct = 0; ct < NT; ct++) {
        const int col0 = ct * 128;
        float acc[16][4] = {};

        #pragma unroll
        for (int half = 0; half < 2; half++) {
            const int qp0 = half * 16;   // pair offset into Q
            __syncthreads();
            #pragma unroll
            for (int p = 0; p < 4; p++) {
                int r = lr + p * 32;
                splitf4(&Kh[r][pc], &Kl[r][pc], pk[p]);
            }
            __syncthreads();
            {
                int nct = half ? ct + 1 : ct;
                int ndk = half ? 0 : 32;
                if (nct < NT) {
                    #pragma unroll
                    for (int p = 0; p < 4; p++)
                        pk[p] = *reinterpret_cast<const float4*>(
                            Km + (size_t)(nct * 128 + lr + p * 32) * DK_ + ndk + lcf);
                }
            }
            #pragma unroll
            for (int kp = 0; kp < 2; kp++) {
                const int p0 = kp * 8;
                unsigned ah[4], al[4];
                ah[0] = Qh[wm0+g  ][qp0+p0+tg]; ah[1] = Qh[wm0+g+8][qp0+p0+tg];
                ah[2] = Qh[wm0+g  ][qp0+p0+tg+4]; ah[3] = Qh[wm0+g+8][qp0+p0+tg+4];
                al[0] = Ql[wm0+g  ][qp0+p0+tg]; al[1] = Ql[wm0+g+8][qp0+p0+tg];
                al[2] = Ql[wm0+g  ][qp0+p0+tg+4]; al[3] = Ql[wm0+g+8][qp0+p0+tg+4];
                #pragma unroll
                for (int nf = 0; nf < 16; nf++) {
                    int r = nf * 8 + g;
                    unsigned bh0 = Kh[r][p0+tg], bh1 = Kh[r][p0+tg+4];
                    unsigned bl0 = Kl[r][p0+tg], bl1 = Kl[r][p0+tg+4];
                    mma16(acc[nf], ah, bh0, bh1);
                    mma16(acc[nf], ah, bl0, bl1);
                    mma16(acc[nf], al, bh0, bh1);
                }
            }
        }

        // --- online stats for rows wm0+g and wm0+g+8 ---
        float tm0 = -1e30f, tm1 = -1e30f;
        #pragma unroll
        for (int nf = 0; nf < 16; nf++) {
            tm0 = fmaxf(tm0, fmaxf(acc[nf][0], acc[nf][1]));
            tm1 = fmaxf(tm1, fmaxf(acc[nf][2], acc[nf][3]));
        }
        tm0 = fmaxf(tm0, __shfl_xor_sync(0xffffffffu, tm0, 1));
        tm0 = fmaxf(tm0, __shfl_xor_sync(0xffffffffu, tm0, 2));
        tm1 = fmaxf(tm1, __shfl_xor_sync(0xffffffffu, tm1, 1));
        tm1 = fmaxf(tm1, __shfl_xor_sync(0xffffffffu, tm1, 2));
        float n0 = fmaxf(m0, tm0), n1 = fmaxf(m1, tm1);
        float e0 = 0.f, e1 = 0.f;
        #pragma unroll
        for (int nf = 0; nf < 16; nf++) {
            e0 += __expf(acc[nf][0] - n0) + __expf(acc[nf][1] - n0);
            e1 += __expf(acc[nf][2] - n1) + __expf(acc[nf][3] - n1);
        }
        e0 += __shfl_xor_sync(0xffffffffu, e0, 1);
        e0 += __shfl_xor_sync(0xffffffffu, e0, 2);
        e1 += __shfl_xor_sync(0xffffffffu, e1, 1);
        e1 += __shfl_xor_sync(0xffffffffu, e1, 2);
        s0 = s0 * __expf(m0 - n0) + e0;  m0 = n0;
        s1 = s1 * __expf(m1 - n1) + e1;  m1 = n1;

        // --- write raw scores ---
        int q0 = row0 + wm0 + g;
        #pragma unroll
        for (int nf = 0; nf < 16; nf++) {
            int c0 = col0 + nf * 8 + 2 * tg;
            *reinterpret_cast<float2*>(&attn[((size_t)bh * S_ + q0) * S_ + c0])
                = make_float2(acc[nf][0], acc[nf][1]);
            *reinterpret_cast<float2*>(&attn[((size_t)bh * S_ + q0 + 8) * S_ + c0])
                = make_float2(acc[nf][2], acc[nf][3]);
        }
    }

    if (tg == 0) {
        int q0 = row0 + wm0 + g;
        g_rmax[bh * S_ + q0]     = m0;
        g_rinv[bh * S_ + q0]     = 1.0f / s0;
        g_rmax[bh * S_ + q0 + 8] = m1;
        g_rinv[bh * S_ + q0 + 8] = 1.0f / s1;
    }
}

// ---------------------------------------------------------------------------
// Kernel 3: normalize weights in place AND ctx = P @ V (1xTF32), prefetched.
// (unchanged from best-measured R6 version)
// ---------------------------------------------------------------------------
__global__ void __launch_bounds__(256) av_kernel(float* __restrict__ attn)
{
    extern __shared__ unsigned sm[];
    unsigned (*AhS)[PSTR] = (unsigned(*)[PSTR])sm;           // 128*36
    unsigned (*VhS)[VSTR] = (unsigned(*)[VSTR])(AhS + 128);  // 32*72
    float* rmaxS = (float*)(VhS + 32);                       // 128
    float* rinvS = rmaxS + 128;                              // 128

    const int bh   = blockIdx.y;
    const int row0 = blockIdx.x * 128;
    const int tid  = threadIdx.x;
    const int warp = tid >> 5;
    const int g = (tid >> 2) & 7, tg = tid & 3;
    const int wm0 = (warp & 3) * 32, wn0 = (warp >> 2) * 32;
    const int lr = tid >> 3, lc = (tid & 7) << 2;
    const int vr = tid >> 4, vc = (tid & 15) << 2;

    if (tid < 128) {
        rmaxS[tid] = g_rmax[bh * S_ + row0 + tid];
        rinvS[tid] = g_rinv[bh * S_ + row0 + tid];
    }

    float* Abase = attn + ((size_t)bh * S_ + row0) * S_;
    const float* Vbase = g_V + (size_t)bh * S_ * DK_;

    float acc[2][4][4] = {};
    float4 pa[4], pv[2];

    #pragma unroll
    for (int p = 0; p < 4; p++)
        pa[p] = *reinterpret_cast<float4*>(Abase + (size_t)(lr + p * 32) * S_ + lc);
    #pragma unroll
    for (int p = 0; p < 2; p++)
        pv[p] = *reinterpret_cast<const float4*>(Vbase + (size_t)(vr + p * 16) * DK_ + vc);
    __syncthreads();

    for (int kb = 0; kb < S_; kb += 32) {
        #pragma unroll
        for (int p = 0; p < 4; p++) {
            int r = lr + p * 32;
            float m = rmaxS[r], inv = rinvS[r];
            float4 v = pa[p];
            v.x = __expf(v.x - m) * inv;
            v.y = __expf(v.y - m) * inv;
            v.z = __expf(v.z - m) * inv;
            v.w = __expf(v.w - m) * inv;
            *reinterpret_cast<float4*>(Abase + (size_t)r * S_ + kb + lc) = v;
            cvt4(&AhS[r][lc], v);
        }
        #pragma unroll
        for (int p = 0; p < 2; p++)
            cvt4(&VhS[vr + p * 16][vc], pv[p]);
        __syncthreads();
        if (kb + 32 < S_) {
            #pragma unroll
            for (int p = 0; p < 4; p++)
                pa[p] = *reinterpret_cast<float4*>(Abase + (size_t)(lr + p * 32) * S_ + kb + 32 + lc);
            #pragma unroll
            for (int p = 0; p < 2; p++)
                pv[p] = *reinterpret_cast<const float4*>(Vbase + (size_t)(kb + 32 + vr + p * 16) * DK_ + vc);
        }
        #pragma unroll
        for (int ks = 0; ks < 32; ks += 8) {
            unsigned ah[2][4];
            #pragma unroll
            for (int mf = 0; mf < 2; mf++) {
                int r = wm0 + mf * 16;
                ah[mf][0] = AhS[r+g  ][ks+tg]; ah[mf][1] = AhS[r+g+8][ks+tg];
                ah[mf][2] = AhS[r+g  ][ks+tg+4]; ah[mf][3] = AhS[r+g+8][ks+tg+4];
            }
            #pragma unroll
            for (int nf = 0; nf < 4; nf++) {
                int vn = wn0 + nf * 8 + g;
                unsigned bh0 = VhS[ks+tg][vn], bh1 = VhS[ks+tg+4][vn];
                #pragma unroll
                for (int mf = 0; mf < 2; mf++)
                    mma8(acc[mf][nf], ah[mf], bh0, bh1);
            }
        }
        __syncthreads();
    }

    const int b = bh >> 4, h = bh & (H_ - 1);
    #pragma unroll
    for (int nf = 0; nf < 4; nf++) {
        int c0 = wn0 + nf * 8 + 2 * tg;
        #pragma unroll
        for (int mf = 0; mf < 2; mf++) {
            int q = row0 + wm0 + mf * 16 + g;
            float2 o0 = make_float2(acc[mf][nf][0], acc[mf][nf][1]);
            float2 o1 = make_float2(acc[mf][nf][2], acc[mf][nf][3]);
            *reinterpret_cast<float2*>(&g_ctx[((size_t)(b * S_ + q))     * D_ + h * DK_ + c0]) = o0;
            *reinterpret_cast<float2*>(&g_ctx[((size_t)(b * S_ + q + 8)) * D_ + h * DK_ + c0]) = o1;
        }
    }
}

// ---------------------------------------------------------------------------
// Kernel 4: output projection out = ctx @ W_o^T + b_o  (bf16x3),
// 256 threads, warp tile 64x32, prefetched.
// ---------------------------------------------------------------------------
__global__ void __launch_bounds__(256) outproj_kernel(
    const float* __restrict__ Wo, const float* __restrict__ bo, float* __restrict__ out)
{
    extern __shared__ unsigned sm[];
    unsigned (*Ah)[ASTR] = (unsigned(*)[ASTR])sm;
    unsigned (*Al)[ASTR] = Ah + 128;
    unsigned (*Bh)[ASTR] = Al + 128;
    unsigned (*Bl)[ASTR] = Bh + 128;

    const int tid = threadIdx.x;
    const int warp = tid >> 5;
    const int g = (tid >> 2) & 7, tg = tid & 3;
    const int wm0 = (warp & 1) * 64, wn0 = (warp >> 1) * 32;
    const int row0 = blockIdx.y * 128;
    const int col0 = blockIdx.x * 128;
    const int lr = tid >> 3, lcf = (tid & 7) << 2, pc = (tid & 7) << 1;

    float acc[4][4][4] = {};
    float4 pa[4], pb[4];

    #pragma unroll
    for (int p = 0; p < 4; p++) {
        pa[p] = *reinterpret_cast<const float4*>(g_ctx + (size_t)(row0 + lr + p * 32) * D_ + lcf);
        pb[p] = *reinterpret_cast<const float4*>(Wo + (size_t)(col0 + lr + p * 32) * D_ + lcf);
    }

    for (int kb = 0; kb < D_; kb += 32) {
        #pragma unroll
        for (int p = 0; p < 4; p++) {
            int r = lr + p * 32;
            splitf4(&Ah[r][pc], &Al[r][pc], pa[p]);
            splitf4(&Bh[r][pc], &Bl[r][pc], pb[p]);
        }
        __syncthreads();
        if (kb + 32 < D_) {
            #pragma unroll
            for (int p = 0; p < 4; p++) {
                pa[p] = *reinterpret_cast<const float4*>(g_ctx + (size_t)(row0 + lr + p * 32) * D_ + kb + 32 + lcf);
                pb[p] = *reinterpret_cast<const float4*>(Wo + (size_t)(col0 + lr + p * 32) * D_ + kb + 32 + lcf);
            }
        }
        #pragma unroll
        for (int kp = 0; kp < 2; kp++) {
            const int p0 = kp * 8;
            unsigned ah[4][4], al[4][4];
            #pragma unroll
            for (int mf = 0; mf < 4; mf++) {
                int r = wm0 + mf * 16;
                ah[mf][0] = Ah[r+g  ][p0+tg]; ah[mf][1] = Ah[r+g+8][p0+tg];
                ah[mf][2] = Ah[r+g  ][p0+tg+4]; ah[mf][3] = Ah[r+g+8][p0+tg+4];
                al[mf][0] = Al[r+g  ][p0+tg]; al[mf][1] = Al[r+g+8][p0+tg];
                al[mf][2] = Al[r+g  ][p0+tg+4]; al[mf][3] = Al[r+g+8][p0+tg+4];
            }
            #pragma unroll
            for (int nf = 0; nf < 4; nf++) {
                int r = wn0 + nf * 8 + g;
                unsigned bh0 = Bh[r][p0+tg], bh1 = Bh[r][p0+tg+4];
                unsigned bl0 = Bl[r][p0+tg], bl1 = Bl[r][p0+tg+4];
                #pragma unroll
                for (int mf = 0; mf < 4; mf++) {
                    mma16(acc[mf][nf], ah[mf], bh0, bh1);
                    mma16(acc[mf][nf], ah[mf], bl0, bl1);
                    mma16(acc[mf][nf], al[mf], bh0, bh1);
                }
            }
        }
        __syncthreads();
    }

    #pragma unroll
    for (int nf = 0; nf < 4; nf++) {
        int n0 = col0 + wn0 + nf * 8 + 2 * tg;
        float b0v = bo[n0], b1v = bo[n0 + 1];
        #pragma unroll
        for (int mf = 0; mf < 4; mf++) {
            int m = row0 + wm0 + mf * 16 + g;
            float2 o0 = make_float2(acc[mf][nf][0] + b0v, acc[mf][nf][1] + b1v);
            float2 o1 = make_float2(acc[mf][nf][2] + b0v, acc[mf][nf][3] + b1v);
            *reinterpret_cast<float2*>(&out[(size_t)m * D_ + n0])       = o0;
            *reinterpret_cast<float2*>(&out[(size_t)(m + 8) * D_ + n0]) = o1;
        }
    }
}

// ---------------------------------------------------------------------------
extern "C" void kernel_launch(void* const* d_in, const int* in_sizes, int n_in,
                              void* d_out, int out_size)
{
    const float* query = (const float*)d_in[0];
    const float* key_  = (const float*)d_in[1];
    const float* value = (const float*)d_in[2];
    const float* W_q = (const float*)d_in[3];
    const float* b_q = (const float*)d_in[4];
    const float* W_k = (const float*)d_in[5];
    const float* b_k = (const float*)d_in[6];
    const float* W_v = (const float*)d_in[7];
    const float* b_v = (const float*)d_in[8];
    const float* W_o = (const float*)d_in[9];
    const float* b_o = (const float*)d_in[10];

    float* out  = (float*)d_out;                       // [B,S,D]
    float* attn = out + (size_t)B_ * S_ * D_;          // [B,H,S,S]

    const int DSMEM  = 4 * 128 * ASTR * sizeof(unsigned);                        // 40960 B
    const int SCSMEM = (2 * 128 * QSTRP + 2 * 128 * ASTR) * sizeof(unsigned);    // 57344 B
    const int AVSMEM = (128 * PSTR + 32 * VSTR) * sizeof(unsigned)
                     + 2 * 128 * sizeof(float);                                  // 28672 B
    cudaFuncSetAttribute(proj_kernel,    cudaFuncAttributeMaxDynamicSharedMemorySize, DSMEM);
    cudaFuncSetAttribute(scores_kernel,  cudaFuncAttributeMaxDynamicSharedMemorySize, SCSMEM);
    cudaFuncSetAttribute(av_kernel,      cudaFuncAttributeMaxDynamicSharedMemorySize, AVSMEM);
    cudaFuncSetAttribute(outproj_kernel, cudaFuncAttributeMaxDynamicSharedMemorySize, DSMEM);

    proj_kernel<<<dim3(D_/128, NROWS/128, 3), 256, DSMEM>>>(
        query, key_, value, W_q, b_q, W_k, b_k, W_v, b_v);

    scores_kernel<<<dim3(S_/128, NBH), 256, SCSMEM>>>(attn);

    av_kernel<<<dim3(S_/128, NBH), 256, AVSMEM>>>(attn);

    outproj_kernel<<<dim3(D_/128, NROWS/128), 256, DSMEM>>>(W_o, b_o, out);
}

// round 15
// speedup vs baseline: 1.0027x; 1.0027x over previous
#include <cuda_runtime.h>
#include <math.h>

#define B_ 2
#define S_ 2048
#define D_ 1024
#define H_ 16
#define DK_ 64
#define NROWS (B_*S_)      // 4096
#define NBH (B_*H_)        // 32

// Scratch (allocation-free): module-load static device memory
__device__ float g_Q[NBH*S_*DK_];   // [b,h,s,dk]
__device__ float g_K[NBH*S_*DK_];
__device__ float g_V[NBH*S_*DK_];
__device__ float g_ctx[(size_t)NROWS*D_];
__device__ float g_rmax[NBH*S_];
__device__ float g_rinv[NBH*S_];

// ---------------------------------------------------------------------------
// bf16x3 helpers: split fp32 into bf16 hi + bf16 lo (≈16 mantissa bits),
// compute hh + hl + lh with bf16 m16n8k16 MMAs (fp32 accumulate).
// ---------------------------------------------------------------------------
// pack {low=x (k even), high=y (k odd)} as bf16x2
__device__ __forceinline__ unsigned packb2(float x, float y) {
    unsigned u;
    asm("cvt.rn.bf16x2.f32 %0, %1, %2;" : "=r"(u) : "f"(y), "f"(x));
    return u;
}
__device__ __forceinline__ void splitb2(float x, float y, unsigned &h, unsigned &l) {
    h = packb2(x, y);
    float hx = __uint_as_float((h & 0xffffu) << 16);
    float hy = __uint_as_float(h & 0xffff0000u);
    l = packb2(x - hx, y - hy);
}
// split a float4 (4 consecutive k) into 2 hi-u32 and 2 lo-u32 (pair-packed)
__device__ __forceinline__ void splitf4(unsigned* h2, unsigned* l2, float4 v) {
    splitb2(v.x, v.y, h2[0], l2[0]);
    splitb2(v.z, v.w, h2[1], l2[1]);
}

// bf16 m16n8k16 mma, accumulate into c[4]
__device__ __forceinline__ void mma16(float* c, const unsigned* a, unsigned b0, unsigned b1) {
    asm volatile(
        "mma.sync.aligned.m16n8k16.row.col.f32.bf16.bf16.f32 "
        "{%0,%1,%2,%3},{%4,%5,%6,%7},{%8,%9},{%0,%1,%2,%3};\n"
        : "+f"(c[0]), "+f"(c[1]), "+f"(c[2]), "+f"(c[3])
        : "r"(a[0]), "r"(a[1]), "r"(a[2]), "r"(a[3]), "r"(b0), "r"(b1));
}
// Fragment indexing (m16n8k16 bf16, pair-units: 1 u32 = 2 k-values):
//  g = lane>>2, tg = lane&3
//  A[m][kp]: a0=(g,tg) a1=(g+8,tg) a2=(g,tg+4) a3=(g+8,tg+4)
//  B^T[n][kp]: b0=(n=g row, tg) b1=(g, tg+4)
//  C[m][n]: c0=(g,2tg) c1=(g,2tg+1) c2=(g+8,2tg) c3=(g+8,2tg+1)  (same as tf32)

// tf32 helpers (av kernel keeps 1xTF32)
__device__ __forceinline__ unsigned cvt_tf32(float f) {
    unsigned u; asm("cvt.rna.tf32.f32 %0, %1;" : "=r"(u) : "f"(f)); return u;
}
__device__ __forceinline__ void cvt4(unsigned* h, float4 v) {
    h[0] = cvt_tf32(v.x); h[1] = cvt_tf32(v.y);
    h[2] = cvt_tf32(v.z); h[3] = cvt_tf32(v.w);
}
__device__ __forceinline__ void mma8(float* c, const unsigned* a, unsigned b0, unsigned b1) {
    asm volatile(
        "mma.sync.aligned.m16n8k8.row.col.f32.tf32.tf32.f32 "
        "{%0,%1,%2,%3},{%4,%5,%6,%7},{%8,%9},{%0,%1,%2,%3};\n"
        : "+f"(c[0]), "+f"(c[1]), "+f"(c[2]), "+f"(c[3])
        : "r"(a[0]), "r"(a[1]), "r"(a[2]), "r"(a[3]), "r"(b0), "r"(b1));
}

#define ASTR 20   // u32 stride for [128 rows][16 pairs] bf16 tiles (20%32=20 -> 4g+tg-ish distinct, verified)
#define QSTRP 36  // u32 stride for [128 rows][32 pairs] Q tiles (36%32=4 -> 4g+tg distinct)
#define PSTR 36   // tf32 [row][32] tiles (av kernel)
#define VSTR 72   // tf32 V [k][64] tiles (av kernel)

// ---------------------------------------------------------------------------
// Kernel 1: QKV projections (bf16x3), 256 threads, warp tile 64x32,
// register-prefetch double buffering.
// ---------------------------------------------------------------------------
__global__ void __launch_bounds__(256) proj_kernel(
    const float* __restrict__ Xq, const float* __restrict__ Xk, const float* __restrict__ Xv,
    const float* __restrict__ Wq, const float* __restrict__ bq,
    const float* __restrict__ Wk, const float* __restrict__ bk,
    const float* __restrict__ Wv, const float* __restrict__ bv)
{
    const int which = blockIdx.z;
    const float* X    = (which == 0) ? Xq : (which == 1) ? Xk : Xv;
    const float* W    = (which == 0) ? Wq : (which == 1) ? Wk : Wv;
    const float* bias = (which == 0) ? bq : (which == 1) ? bk : bv;
    float* Out        = (which == 0) ? g_Q : (which == 1) ? g_K : g_V;

    extern __shared__ unsigned sm[];
    unsigned (*Ah)[ASTR] = (unsigned(*)[ASTR])sm;   // 128 x 20
    unsigned (*Al)[ASTR] = Ah + 128;
    unsigned (*Bh)[ASTR] = Al + 128;
    unsigned (*Bl)[ASTR] = Bh + 128;

    const int tid = threadIdx.x;
    const int warp = tid >> 5;
    const int g = (tid >> 2) & 7, tg = tid & 3;
    const int wm0 = (warp & 1) * 64, wn0 = (warp >> 1) * 32;
    const int row0 = blockIdx.y * 128;
    const int col0 = blockIdx.x * 128;
    const int lr = tid >> 3;                 // 32 rows per pass
    const int lcf = (tid & 7) << 2;          // float col
    const int pc  = (tid & 7) << 1;          // pair col

    float acc[4][4][4] = {};
    float4 pa[4], pb[4];

    #pragma unroll
    for (int p = 0; p < 4; p++) {
        pa[p] = *reinterpret_cast<const float4*>(X + (size_t)(row0 + lr + p * 32) * D_ + lcf);
        pb[p] = *reinterpret_cast<const float4*>(W + (size_t)(col0 + lr + p * 32) * D_ + lcf);
    }

    for (int kb = 0; kb < D_; kb += 32) {
        #pragma unroll
        for (int p = 0; p < 4; p++) {
            int r = lr + p * 32;
            splitf4(&Ah[r][pc], &Al[r][pc], pa[p]);
            splitf4(&Bh[r][pc], &Bl[r][pc], pb[p]);
        }
        __syncthreads();
        if (kb + 32 < D_) {
            #pragma unroll
            for (int p = 0; p < 4; p++) {
                pa[p] = *reinterpret_cast<const float4*>(X + (size_t)(row0 + lr + p * 32) * D_ + kb + 32 + lcf);
                pb[p] = *reinterpret_cast<const float4*>(W + (size_t)(col0 + lr + p * 32) * D_ + kb + 32 + lcf);
            }
        }
        #pragma unroll
        for (int kp = 0; kp < 2; kp++) {       // two k16 blocks per 32-float chunk
            const int p0 = kp * 8;
            unsigned ah[4][4], al[4][4];
            #pragma unroll
            for (int mf = 0; mf < 4; mf++) {
                int r = wm0 + mf * 16;
                ah[mf][0] = Ah[r+g  ][p0+tg]; ah[mf][1] = Ah[r+g+8][p0+tg];
                ah[mf][2] = Ah[r+g  ][p0+tg+4]; ah[mf][3] = Ah[r+g+8][p0+tg+4];
                al[mf][0] = Al[r+g  ][p0+tg]; al[mf][1] = Al[r+g+8][p0+tg];
                al[mf][2] = Al[r+g  ][p0+tg+4]; al[mf][3] = Al[r+g+8][p0+tg+4];
            }
            #pragma unroll
            for (int nf = 0; nf < 4; nf++) {
                int r = wn0 + nf * 8 + g;
                unsigned bh0 = Bh[r][p0+tg], bh1 = Bh[r][p0+tg+4];
                unsigned bl0 = Bl[r][p0+tg], bl1 = Bl[r][p0+tg+4];
                #pragma unroll
                for (int mf = 0; mf < 4; mf++) {
                    mma16(acc[mf][nf], ah[mf], bh0, bh1);
                    mma16(acc[mf][nf], ah[mf], bl0, bl1);
                    mma16(acc[mf][nf], al[mf], bh0, bh1);
                }
            }
        }
        __syncthreads();
    }

    // Epilogue: bias + split-head store Out[((b*H+h)*S+s)*DK+dk]
    #pragma unroll
    for (int nf = 0; nf < 4; nf++) {
        int n0 = col0 + wn0 + nf * 8 + 2 * tg;
        float b0v = bias[n0], b1v = bias[n0 + 1];
        int h = n0 >> 6, dk = n0 & (DK_ - 1);
        #pragma unroll
        for (int mf = 0; mf < 4; mf++) {
            int m = row0 + wm0 + mf * 16 + g;
            int b = m >> 11, s = m & (S_ - 1);
            size_t base = (((size_t)(b * H_ + h)) * S_) * DK_ + dk;
            float2 o0 = make_float2(acc[mf][nf][0] + b0v, acc[mf][nf][1] + b1v);
            float2 o1 = make_float2(acc[mf][nf][2] + b0v, acc[mf][nf][3] + b1v);
            *reinterpret_cast<float2*>(&Out[base + (size_t)s * DK_])       = o0;
            *reinterpret_cast<float2*>(&Out[base + (size_t)(s + 8) * DK_]) = o1;
        }
    }
}

// ---------------------------------------------------------------------------
// Kernel 2: scores = (Q*scale) @ K^T (bf16x3) + fused online softmax stats,
// register prefetch of K chunks. 256 threads, warp owns 16 q rows.
// ---------------------------------------------------------------------------
__global__ void __launch_bounds__(256) scores_kernel(float* __restrict__ attn)
{
    extern __shared__ unsigned sm[];
    unsigned (*Qh)[QSTRP] = (unsigned(*)[QSTRP])sm;          // 128 x 36 (32 pairs)
    unsigned (*Ql)[QSTRP] = Qh + 128;
    unsigned (*Kh)[ASTR]  = (unsigned(*)[ASTR])(Ql + 128);   // 128 x 20 (16 pairs)
    unsigned (*Kl)[ASTR]  = Kh + 128;

    const int bh   = blockIdx.y;
    const int row0 = blockIdx.x * 128;
    const int tid  = threadIdx.x;
    const int warp = tid >> 5;
    const int g = (tid >> 2) & 7, tg = tid & 3;
    const int wm0 = warp * 16;
    const int lr = tid >> 3, lcf = (tid & 7) << 2, pc = (tid & 7) << 1;
    const int NT = S_ / 128;

    const float* Qm = g_Q + ((size_t)bh * S_ + row0) * DK_;
    const float* Km = g_K + (size_t)bh * S_ * DK_;

    // Stage whole Q strip (128 x 64 floats = 32 pairs), scaled, hi/lo split.
    #pragma unroll
    for (int p = 0; p < 8; p++) {
        int lin = tid + (p << 8);
        int r = lin >> 4, cf = (lin & 15) << 2;
        float4 v = *reinterpret_cast<const float4*>(Qm + (size_t)r * DK_ + cf);
        v.x *= 0.125f; v.y *= 0.125f; v.z *= 0.125f; v.w *= 0.125f;
        splitf4(&Qh[r][cf >> 1], &Ql[r][cf >> 1], v);
    }

    float4 pk[4];
    #pragma unroll
    for (int p = 0; p < 4; p++)
        pk[p] = *reinterpret_cast<const float4*>(Km + (size_t)(lr + p * 32) * DK_ + lcf);

    float m0 = -1e30f, m1 = -1e30f, s0 = 0.f, s1 = 0.f;

    for (int ct = 0; ct < NT; ct++) {
        const int col0 = ct * 128;
        float acc[16][4] = {};

        #pragma unroll
        for (int half = 0; half < 2; half++) {
            const int qp0 = half * 16;   // pair offset into Q
            __syncthreads();
            #pragma unroll
            for (int p = 0; p < 4; p++) {
                int r = lr + p * 32;
                splitf4(&Kh[r][pc], &Kl[r][pc], pk[p]);
            }
            __syncthreads();
            {
                int nct = half ? ct + 1 : ct;
                int ndk = half ? 0 : 32;
                if (nct < NT) {
                    #pragma unroll
                    for (int p = 0; p < 4; p++)
                        pk[p] = *reinterpret_cast<const float4*>(
                            Km + (size_t)(nct * 128 + lr + p * 32) * DK_ + ndk + lcf);
                }
            }
            #pragma unroll
            for (int kp = 0; kp < 2; kp++) {
                const int p0 = kp * 8;
                unsigned ah[4], al[4];
                ah[0] = Qh[wm0+g  ][qp0+p0+tg]; ah[1] = Qh[wm0+g+8][qp0+p0+tg];
                ah[2] = Qh[wm0+g  ][qp0+p0+tg+4]; ah[3] = Qh[wm0+g+8][qp0+p0+tg+4];
                al[0] = Ql[wm0+g  ][qp0+p0+tg]; al[1] = Ql[wm0+g+8][qp0+p0+tg];
                al[2] = Ql[wm0+g  ][qp0+p0+tg+4]; al[3] = Ql[wm0+g+8][qp0+p0+tg+4];
                #pragma unroll
                for (int nf = 0; nf < 16; nf++) {
                    int r = nf * 8 + g;
                    unsigned bh0 = Kh[r][p0+tg], bh1 = Kh[r][p0+tg+4];
                    unsigned bl0 = Kl[r][p0+tg], bl1 = Kl[r][p0+tg+4];
                    mma16(acc[nf], ah, bh0, bh1);
                    mma16(acc[nf], ah, bl0, bl1);
                    mma16(acc[nf], al, bh0, bh1);
                }
            }
        }

        // --- online stats for rows wm0+g and wm0+g+8 ---
        float tm0 = -1e30f, tm1 = -1e30f;
        #pragma unroll
        for (int nf = 0; nf < 16; nf++) {
            tm0 = fmaxf(tm0, fmaxf(acc[nf][0], acc[nf][1]));
            tm1 = fmaxf(tm1, fmaxf(acc[nf][2], acc[nf][3]));
        }
        tm0 = fmaxf(tm0, __shfl_xor_sync(0xffffffffu, tm0, 1));
        tm0 = fmaxf(tm0, __shfl_xor_sync(0xffffffffu, tm0, 2));
        tm1 = fmaxf(tm1, __shfl_xor_sync(0xffffffffu, tm1, 1));
        tm1 = fmaxf(tm1, __shfl_xor_sync(0xffffffffu, tm1, 2));
        float n0 = fmaxf(m0, tm0), n1 = fmaxf(m1, tm1);
        float e0 = 0.f, e1 = 0.f;
        #pragma unroll
        for (int nf = 0; nf < 16; nf++) {
            e0 += __expf(acc[nf][0] - n0) + __expf(acc[nf][1] - n0);
            e1 += __expf(acc[nf][2] - n1) + __expf(acc[nf][3] - n1);
        }
        e0 += __shfl_xor_sync(0xffffffffu, e0, 1);
        e0 += __shfl_xor_sync(0xffffffffu, e0, 2);
        e1 += __shfl_xor_sync(0xffffffffu, e1, 1);
        e1 += __shfl_xor_sync(0xffffffffu, e1, 2);
        s0 = s0 * __expf(m0 - n0) + e0;  m0 = n0;
        s1 = s1 * __expf(m1 - n1) + e1;  m1 = n1;

        // --- write raw scores ---
        int q0 = row0 + wm0 + g;
        #pragma unroll
        for (int nf = 0; nf < 16; nf++) {
            int c0 = col0 + nf * 8 + 2 * tg;
            *reinterpret_cast<float2*>(&attn[((size_t)bh * S_ + q0) * S_ + c0])
                = make_float2(acc[nf][0], acc[nf][1]);
            *reinterpret_cast<float2*>(&attn[((size_t)bh * S_ + q0 + 8) * S_ + c0])
                = make_float2(acc[nf][2], acc[nf][3]);
        }
    }

    if (tg == 0) {
        int q0 = row0 + wm0 + g;
        g_rmax[bh * S_ + q0]     = m0;
        g_rinv[bh * S_ + q0]     = 1.0f / s0;
        g_rmax[bh * S_ + q0 + 8] = m1;
        g_rinv[bh * S_ + q0 + 8] = 1.0f / s1;
    }
}

// ---------------------------------------------------------------------------
// Kernel 3: normalize weights in place AND ctx = P @ V (1xTF32), prefetched.
// (unchanged from best-measured R6 version)
// ---------------------------------------------------------------------------
__global__ void __launch_bounds__(256) av_kernel(float* __restrict__ attn)
{
    extern __shared__ unsigned sm[];
    unsigned (*AhS)[PSTR] = (unsigned(*)[PSTR])sm;           // 128*36
    unsigned (*VhS)[VSTR] = (unsigned(*)[VSTR])(AhS + 128);  // 32*72
    float* rmaxS = (float*)(VhS + 32);                       // 128
    float* rinvS = rmaxS + 128;                              // 128

    const int bh   = blockIdx.y;
    const int row0 = blockIdx.x * 128;
    const int tid  = threadIdx.x;
    const int warp = tid >> 5;
    const int g = (tid >> 2) & 7, tg = tid & 3;
    const int wm0 = (warp & 3) * 32, wn0 = (warp >> 2) * 32;
    const int lr = tid >> 3, lc = (tid & 7) << 2;
    const int vr = tid >> 4, vc = (tid & 15) << 2;

    if (tid < 128) {
        rmaxS[tid] = g_rmax[bh * S_ + row0 + tid];
        rinvS[tid] = g_rinv[bh * S_ + row0 + tid];
    }

    float* Abase = attn + ((size_t)bh * S_ + row0) * S_;
    const float* Vbase = g_V + (size_t)bh * S_ * DK_;

    float acc[2][4][4] = {};
    float4 pa[4], pv[2];

    #pragma unroll
    for (int p = 0; p < 4; p++)
        pa[p] = *reinterpret_cast<float4*>(Abase + (size_t)(lr + p * 32) * S_ + lc);
    #pragma unroll
    for (int p = 0; p < 2; p++)
        pv[p] = *reinterpret_cast<const float4*>(Vbase + (size_t)(vr + p * 16) * DK_ + vc);
    __syncthreads();

    for (int kb = 0; kb < S_; kb += 32) {
        #pragma unroll
        for (int p = 0; p < 4; p++) {
            int r = lr + p * 32;
            float m = rmaxS[r], inv = rinvS[r];
            float4 v = pa[p];
            v.x = __expf(v.x - m) * inv;
            v.y = __expf(v.y - m) * inv;
            v.z = __expf(v.z - m) * inv;
            v.w = __expf(v.w - m) * inv;
            *reinterpret_cast<float4*>(Abase + (size_t)r * S_ + kb + lc) = v;
            cvt4(&AhS[r][lc], v);
        }
        #pragma unroll
        for (int p = 0; p < 2; p++)
            cvt4(&VhS[vr + p * 16][vc], pv[p]);
        __syncthreads();
        if (kb + 32 < S_) {
            #pragma unroll
            for (int p = 0; p < 4; p++)
                pa[p] = *reinterpret_cast<float4*>(Abase + (size_t)(lr + p * 32) * S_ + kb + 32 + lc);
            #pragma unroll
            for (int p = 0; p < 2; p++)
                pv[p] = *reinterpret_cast<const float4*>(Vbase + (size_t)(kb + 32 + vr + p * 16) * DK_ + vc);
        }
        #pragma unroll
        for (int ks = 0; ks < 32; ks += 8) {
            unsigned ah[2][4];
            #pragma unroll
            for (int mf = 0; mf < 2; mf++) {
                int r = wm0 + mf * 16;
                ah[mf][0] = AhS[r+g  ][ks+tg]; ah[mf][1] = AhS[r+g+8][ks+tg];
                ah[mf][2] = AhS[r+g  ][ks+tg+4]; ah[mf][3] = AhS[r+g+8][ks+tg+4];
            }
            #pragma unroll
            for (int nf = 0; nf < 4; nf++) {
                int vn = wn0 + nf * 8 + g;
                unsigned bh0 = VhS[ks+tg][vn], bh1 = VhS[ks+tg+4][vn];
                #pragma unroll
                for (int mf = 0; mf < 2; mf++)
                    mma8(acc[mf][nf], ah[mf], bh0, bh1);
            }
        }
        __syncthreads();
    }

    const int b = bh >> 4, h = bh & (H_ - 1);
    #pragma unroll
    for (int nf = 0; nf < 4; nf++) {
        int c0 = wn0 + nf * 8 + 2 * tg;
        #pragma unroll
        for (int mf = 0; mf < 2; mf++) {
            int q = row0 + wm0 + mf * 16 + g;
            float2 o0 = make_float2(acc[mf][nf][0], acc[mf][nf][1]);
            float2 o1 = make_float2(acc[mf][nf][2], acc[mf][nf][3]);
            *reinterpret_cast<float2*>(&g_ctx[((size_t)(b * S_ + q))     * D_ + h * DK_ + c0]) = o0;
            *reinterpret_cast<float2*>(&g_ctx[((size_t)(b * S_ + q + 8)) * D_ + h * DK_ + c0]) = o1;
        }
    }
}

// ---------------------------------------------------------------------------
// Kernel 4: output projection out = ctx @ W_o^T + b_o  (bf16x3),
// 256 threads, warp tile 64x32, prefetched.
// ---------------------------------------------------------------------------
__global__ void __launch_bounds__(256) outproj_kernel(
    const float* __restrict__ Wo, const float* __restrict__ bo, float* __restrict__ out)
{
    extern __shared__ unsigned sm[];
    unsigned (*Ah)[ASTR] = (unsigned(*)[ASTR])sm;
    unsigned (*Al)[ASTR] = Ah + 128;
    unsigned (*Bh)[ASTR] = Al + 128;
    unsigned (*Bl)[ASTR] = Bh + 128;

    const int tid = threadIdx.x;
    const int warp = tid >> 5;
    const int g = (tid >> 2) & 7, tg = tid & 3;
    const int wm0 = (warp & 1) * 64, wn0 = (warp >> 1) * 32;
    const int row0 = blockIdx.y * 128;
    const int col0 = blockIdx.x * 128;
    const int lr = tid >> 3, lcf = (tid & 7) << 2, pc = (tid & 7) << 1;

    float acc[4][4][4] = {};
    float4 pa[4], pb[4];

    #pragma unroll
    for (int p = 0; p < 4; p++) {
        pa[p] = *reinterpret_cast<const float4*>(g_ctx + (size_t)(row0 + lr + p * 32) * D_ + lcf);
        pb[p] = *reinterpret_cast<const float4*>(Wo + (size_t)(col0 + lr + p * 32) * D_ + lcf);
    }

    for (int kb = 0; kb < D_; kb += 32) {
        #pragma unroll
        for (int p = 0; p < 4; p++) {
            int r = lr + p * 32;
            splitf4(&Ah[r][pc], &Al[r][pc], pa[p]);
            splitf4(&Bh[r][pc], &Bl[r][pc], pb[p]);
        }
        __syncthreads();
        if (kb + 32 < D_) {
            #pragma unroll
            for (int p = 0; p < 4; p++) {
                pa[p] = *reinterpret_cast<const float4*>(g_ctx + (size_t)(row0 + lr + p * 32) * D_ + kb + 32 + lcf);
                pb[p] = *reinterpret_cast<const float4*>(Wo + (size_t)(col0 + lr + p * 32) * D_ + kb + 32 + lcf);
            }
        }
        #pragma unroll
        for (int kp = 0; kp < 2; kp++) {
            const int p0 = kp * 8;
            unsigned ah[4][4], al[4][4];
            #pragma unroll
            for (int mf = 0; mf < 4; mf++) {
                int r = wm0 + mf * 16;
                ah[mf][0] = Ah[r+g  ][p0+tg]; ah[mf][1] = Ah[r+g+8][p0+tg];
                ah[mf][2] = Ah[r+g  ][p0+tg+4]; ah[mf][3] = Ah[r+g+8][p0+tg+4];
                al[mf][0] = Al[r+g  ][p0+tg]; al[mf][1] = Al[r+g+8][p0+tg];
                al[mf][2] = Al[r+g  ][p0+tg+4]; al[mf][3] = Al[r+g+8][p0+tg+4];
            }
            #pragma unroll
            for (int nf = 0; nf < 4; nf++) {
                int r = wn0 + nf * 8 + g;
                unsigned bh0 = Bh[r][p0+tg], bh1 = Bh[r][p0+tg+4];
                unsigned bl0 = Bl[r][p0+tg], bl1 = Bl[r][p0+tg+4];
                #pragma unroll
                for (int mf = 0; mf < 4; mf++) {
                    mma16(acc[mf][nf], ah[mf], bh0, bh1);
                    mma16(acc[mf][nf], ah[mf], bl0, bl1);
                    mma16(acc[mf][nf], al[mf], bh0, bh1);
                }
            }
        }
        __syncthreads();
    }

    #pragma unroll
    for (int nf = 0; nf < 4; nf++) {
        int n0 = col0 + wn0 + nf * 8 + 2 * tg;
        float b0v = bo[n0], b1v = bo[n0 + 1];
        #pragma unroll
        for (int mf = 0; mf < 4; mf++) {
            int m = row0 + wm0 + mf * 16 + g;
            float2 o0 = make_float2(acc[mf][nf][0] + b0v, acc[mf][nf][1] + b1v);
            float2 o1 = make_float2(acc[mf][nf][2] + b0v, acc[mf][nf][3] + b1v);
            *reinterpret_cast<float2*>(&out[(size_t)m * D_ + n0])       = o0;
            *reinterpret_cast<float2*>(&out[(size_t)(m + 8) * D_ + n0]) = o1;
        }
    }
}

// ---------------------------------------------------------------------------
extern "C" void kernel_launch(void* const* d_in, const int* in_sizes, int n_in,
                              void* d_out, int out_size)
{
    const float* query = (const float*)d_in[0];
    const float* key_  = (const float*)d_in[1];
    const float* value = (const float*)d_in[2];
    const float* W_q = (const float*)d_in[3];
    const float* b_q = (const float*)d_in[4];
    const float* W_k = (const float*)d_in[5];
    const float* b_k = (const float*)d_in[6];
    const float* W_v = (const float*)d_in[7];
    const float* b_v = (const float*)d_in[8];
    const float* W_o = (const float*)d_in[9];
    const float* b_o = (const float*)d_in[10];

    float* out  = (float*)d_out;                       // [B,S,D]
    float* attn = out + (size_t)B_ * S_ * D_;          // [B,H,S,S]

    const int DSMEM  = 4 * 128 * ASTR * sizeof(unsigned);                        // 40960 B
    const int SCSMEM = (2 * 128 * QSTRP + 2 * 128 * ASTR) * sizeof(unsigned);    // 57344 B
    const int AVSMEM = (128 * PSTR + 32 * VSTR) * sizeof(unsigned)
                     + 2 * 128 * sizeof(float);                                  // 28672 B
    cudaFuncSetAttribute(proj_kernel,    cudaFuncAttributeMaxDynamicSharedMemorySize, DSMEM);
    cudaFuncSetAttribute(scores_kernel,  cudaFuncAttributeMaxDynamicSharedMemorySize, SCSMEM);
    cudaFuncSetAttribute(av_kernel,      cudaFuncAttributeMaxDynamicSharedMemorySize, AVSMEM);
    cudaFuncSetAttribute(outproj_kernel, cudaFuncAttributeMaxDynamicSharedMemorySize, DSMEM);

    proj_kernel<<<dim3(D_/128, NROWS/128, 3), 256, DSMEM>>>(
        query, key_, value, W_q, b_q, W_k, b_k, W_v, b_v);

    scores_kernel<<<dim3(S_/128, NBH), 256, SCSMEM>>>(attn);

    av_kernel<<<dim3(S_/128, NBH), 256, AVSMEM>>>(attn);

    outproj_kernel<<<dim3(D_/128, NROWS/128), 256, DSMEM>>>(W_o, b_o, out);
}